// round 1
// baseline (speedup 1.0000x reference)
#include <cuda_runtime.h>
#include <math.h>

#define G_    2
#define NP_   332
#define NN_   664
#define DEG_  32
#define NE_   21248
#define D_    332
#define KH_   6
#define K1_   166
#define K2_   83
#define KCAT_ 2324
#define D3_   128
#define SPLITK 4
#define MAXDEG 352
#define BM 64
#define BN 64
#define BK 16

__device__ float g_H[NN_ * 8];
__device__ float g_A[(size_t)NN_ * KCAT_];
__device__ float g_part[SPLITK][NN_ * D_];
__device__ float g_xt[NN_ * D_];
__device__ float g_conv[NN_ * D_];
__device__ float g_score[NN_];
__device__ float g_hp[NP_ * D_];
__device__ float g_hp2[G_ * K2_ * D_];
__device__ float g_z[G_ * 1328];
__device__ int   g_perm1[G_ * K1_];
__device__ int   g_perm2[G_ * K2_];
__device__ int   g_newidx[NN_];
__device__ int   g_cnt[NN_], g_cur[NN_], g_off[NN_ + 1];
__device__ int   g_cnt2[NP_], g_cur2[NP_], g_off2[NP_ + 1];
__device__ int   g_el[NE_], g_el2[NE_];

__global__ void k_zero() {
    int t = blockIdx.x * blockDim.x + threadIdx.x;
    if (t < NN_) { g_cnt[t] = 0; g_cur[t] = 0; }
    if (t < NP_) { g_cnt2[t] = 0; g_cur2[t] = 0; }
}

__global__ void k_gates(const float* __restrict__ pos, const float* __restrict__ W1,
                        int n, int usePerm) {
    int gt = blockIdx.x * blockDim.x + threadIdx.x;
    int w = gt >> 5, lane = gt & 31;
    if (w >= n) return;
    int row = usePerm ? g_perm1[w] : w;
    const float* p = pos + (size_t)row * D_;
    float acc[KH_];
#pragma unroll
    for (int k = 0; k < KH_; k++) acc[k] = 0.f;
    for (int i = lane; i < D_; i += 32) {
        float pv = p[i];
#pragma unroll
        for (int k = 0; k < KH_; k++) acc[k] += pv * W1[i * KH_ + k];
    }
#pragma unroll
    for (int k = 0; k < KH_; k++)
#pragma unroll
        for (int o = 16; o; o >>= 1) acc[k] += __shfl_xor_sync(0xffffffffu, acc[k], o);
    if (lane == 0) {
#pragma unroll
        for (int k = 0; k < KH_; k++) g_H[w * 8 + k] = fmaxf(acc[k], 0.f);
        g_H[w * 8 + KH_] = 1.f;
    }
}

__global__ void k_expand(const float* __restrict__ xin, int n, int useHp) {
    int r = blockIdx.x;
    if (r >= n) return;
    const float* x = (useHp ? g_hp : xin) + (size_t)r * D_;
    float h[7];
#pragma unroll
    for (int k = 0; k < 7; k++) h[k] = g_H[r * 8 + k];
    float* out = g_A + (size_t)r * KCAT_;
    for (int c = threadIdx.x; c < KCAT_; c += blockDim.x) {
        int k = c / D_, i = c - k * D_;
        out[c] = h[k] * x[i];
    }
}

__global__ void k_gemm(const float* __restrict__ W2, const float* __restrict__ nb, int M) {
    __shared__ float As[BK][BM + 1];
    __shared__ float Bs[BK][BN + 4];
    const int KSPL = (KCAT_ + SPLITK - 1) / SPLITK;
    int bn = blockIdx.x * BN, bm = blockIdx.y * BM, z = blockIdx.z;
    int k_begin = z * KSPL;
    int k_end = min(KCAT_, k_begin + KSPL);
    int tid = threadIdx.x;
    int ty = tid >> 4, tx = tid & 15;
    float acc[4][4];
#pragma unroll
    for (int i = 0; i < 4; i++)
#pragma unroll
        for (int j = 0; j < 4; j++) acc[i][j] = 0.f;

    for (int k0 = k_begin; k0 < k_end; k0 += BK) {
        for (int idx = tid; idx < BM * BK; idx += 256) {
            int ml = idx >> 4, kl = idx & 15;
            int m = bm + ml, k = k0 + kl;
            As[kl][ml] = (m < M && k < k_end) ? g_A[(size_t)m * KCAT_ + k] : 0.f;
        }
        for (int idx = tid; idx < BK * BN; idx += 256) {
            int kl = idx >> 6, j = idx & 63;
            int k = k0 + kl, o = bn + j;
            float v = 0.f;
            if (k < k_end && o < D_)
                v = (k < 6 * D_) ? W2[(size_t)k * D_ + o] : nb[(size_t)(k - 6 * D_) * D_ + o];
            Bs[kl][j] = v;
        }
        __syncthreads();
#pragma unroll
        for (int kk = 0; kk < BK; kk++) {
            float a[4], b[4];
#pragma unroll
            for (int i = 0; i < 4; i++) a[i] = As[kk][ty * 4 + i];
#pragma unroll
            for (int j = 0; j < 4; j++) b[j] = Bs[kk][tx * 4 + j];
#pragma unroll
            for (int i = 0; i < 4; i++)
#pragma unroll
                for (int j = 0; j < 4; j++) acc[i][j] += a[i] * b[j];
        }
        __syncthreads();
    }
#pragma unroll
    for (int i = 0; i < 4; i++) {
        int m = bm + ty * 4 + i;
        if (m < M)
#pragma unroll
            for (int j = 0; j < 4; j++) {
                int o = bn + tx * 4 + j;
                if (o < D_) g_part[z][m * D_ + o] = acc[i][j];
            }
    }
}

__global__ void k_reduce(int M) {
    int t = blockIdx.x * blockDim.x + threadIdx.x;
    if (t < M * D_) {
        float s = 0.f;
#pragma unroll
        for (int z = 0; z < SPLITK; z++) s += g_part[z][t];
        g_xt[t] = s;
    }
}

__global__ void k_count1(const int* __restrict__ dst) {
    int e = blockIdx.x * blockDim.x + threadIdx.x;
    if (e < NE_) atomicAdd(&g_cnt[dst[e]], 1);
}

__global__ void k_scan(int stage) {
    __shared__ int s[1024];
    int n = stage ? NP_ : NN_;
    const int* cnt = stage ? g_cnt2 : g_cnt;
    int* off = stage ? g_off2 : g_off;
    int t = threadIdx.x;
    s[t] = (t < n) ? cnt[t] : 0;
    __syncthreads();
    for (int d = 1; d < 1024; d <<= 1) {
        int u = (t >= d) ? s[t - d] : 0;
        __syncthreads();
        s[t] += u;
        __syncthreads();
    }
    if (t < n) off[t + 1] = s[t];
    if (t == 0) off[0] = 0;
}

__global__ void k_scatter1(const int* __restrict__ dst) {
    int e = blockIdx.x * blockDim.x + threadIdx.x;
    if (e < NE_) {
        int d = dst[e];
        int p = atomicAdd(&g_cur[d], 1);
        g_el[g_off[d] + p] = e;
    }
}

__global__ void k_count2(const int* __restrict__ src, const int* __restrict__ dst) {
    int e = blockIdx.x * blockDim.x + threadIdx.x;
    if (e < NE_) {
        int ns = g_newidx[src[e]], nd = g_newidx[dst[e]];
        if (ns >= 0 && nd >= 0) atomicAdd(&g_cnt2[nd], 1);
    }
}

__global__ void k_scatter2(const int* __restrict__ src, const int* __restrict__ dst) {
    int e = blockIdx.x * blockDim.x + threadIdx.x;
    if (e < NE_) {
        int ns = g_newidx[src[e]], nd = g_newidx[dst[e]];
        if (ns >= 0 && nd >= 0) {
            int p = atomicAdd(&g_cur2[nd], 1);
            g_el2[g_off2[nd] + p] = e;
        }
    }
}

__global__ void k_agg(const float* __restrict__ attr, const int* __restrict__ src,
                      const float* __restrict__ bias, int n, int stage) {
    int d = blockIdx.x;
    if (d >= n) return;
    const int* off = stage ? g_off2 : g_off;
    const int* el = stage ? g_el2 : g_el;
    int s0 = off[d], cnt = off[d + 1] - s0;
    __shared__ float w[MAXDEG];
    __shared__ int sn[MAXDEG];
    __shared__ float sh_wself, sh_inv;
    int tid = threadIdx.x;
    for (int i = tid; i < cnt; i += blockDim.x) {
        int e = el[s0 + i];
        w[i] = attr[e];
        int s = src[e];
        sn[i] = stage ? g_newidx[s] : s;
    }
    __syncthreads();
    if (tid < 32) {
        float mx = 1.0f;
        for (int i = tid; i < cnt; i += 32) mx = fmaxf(mx, w[i]);
#pragma unroll
        for (int o = 16; o; o >>= 1) mx = fmaxf(mx, __shfl_xor_sync(0xffffffffu, mx, o));
        float sm = (tid == 0) ? __expf(1.f - mx) : 0.f;
        for (int i = tid; i < cnt; i += 32) {
            float e_ = __expf(w[i] - mx);
            w[i] = e_;
            sm += e_;
        }
#pragma unroll
        for (int o = 16; o; o >>= 1) sm += __shfl_xor_sync(0xffffffffu, sm, o);
        if (tid == 0) {
            float inv = 1.f / sm;
            sh_inv = inv;
            sh_wself = __expf(1.f - mx) * inv;
        }
    }
    __syncthreads();
    float wself = sh_wself, inv = sh_inv;
    for (int o = tid; o < D_; o += blockDim.x) {
        float acc = 0.f;
        for (int i = 0; i < cnt; i++) acc += w[i] * g_xt[(size_t)sn[i] * D_ + o];
        g_conv[(size_t)d * D_ + o] = acc * inv + wself * g_xt[(size_t)d * D_ + o] + bias[o];
    }
}

__global__ void k_score(const float* __restrict__ pw, int n) {
    int gt = blockIdx.x * blockDim.x + threadIdx.x;
    int w = gt >> 5, lane = gt & 31;
    if (w >= n) return;
    float nrm = 0.f, dot = 0.f;
    for (int i = lane; i < D_; i += 32) {
        float wv = pw[i];
        nrm += wv * wv;
        dot += g_conv[(size_t)w * D_ + i] * wv;
    }
#pragma unroll
    for (int o = 16; o; o >>= 1) {
        nrm += __shfl_xor_sync(0xffffffffu, nrm, o);
        dot += __shfl_xor_sync(0xffffffffu, dot, o);
    }
    if (lane == 0) {
        float v = dot * rsqrtf(nrm);
        g_score[w] = 1.f / (1.f + __expf(-v));
    }
}

__global__ void k_select(int nper, int k, int stage) {
    int gi = blockIdx.x;
    __shared__ float s[NP_];
    int t = threadIdx.x;
    int node = gi * nper + t;
    s[t] = g_score[node];
    __syncthreads();
    float mine = s[t];
    int rank = 0;
    for (int j = 0; j < nper; j++) {
        float sj = s[j];
        rank += (sj > mine) || (sj == mine && j < t);
    }
    if (stage == 0) {
        g_newidx[node] = (rank < k) ? gi * k + rank : -1;
        if (rank < k) g_perm1[gi * k + rank] = node;
    } else {
        if (rank < k) g_perm2[gi * k + rank] = node;
    }
}

__global__ void k_gather(int stage) {
    int j = blockIdx.x;
    int old = stage ? g_perm2[j] : g_perm1[j];
    float sc = g_score[old];
    float* out = stage ? g_hp2 : g_hp;
    for (int o = threadIdx.x; o < D_; o += blockDim.x)
        out[(size_t)j * D_ + o] = g_conv[(size_t)old * D_ + o] * sc;
}

__global__ void k_readout(int k, float inv, int zoff, int stage) {
    int gi = blockIdx.x;
    const float* f = stage ? g_hp2 : g_hp;
    for (int o = threadIdx.x; o < D_; o += blockDim.x) {
        float mx = -3.4e38f, sm = 0.f;
        for (int j = 0; j < k; j++) {
            float v = f[(size_t)(gi * k + j) * D_ + o];
            mx = fmaxf(mx, v);
            sm += v;
        }
        g_z[gi * 1328 + zoff + o] = mx;
        g_z[gi * 1328 + zoff + D_ + o] = sm * inv;
    }
}

__global__ void k_head(const float* __restrict__ fc1W, const float* __restrict__ fc1b,
                       const float* __restrict__ bn1g, const float* __restrict__ bn1b,
                       const float* __restrict__ fc2W, const float* __restrict__ fc2b,
                       const float* __restrict__ bn2g, const float* __restrict__ bn2b,
                       const float* __restrict__ fc3W, const float* __restrict__ fc3b,
                       float* __restrict__ out) {
    __shared__ float a1[2][D_];
    __shared__ float a2[2][D3_];
    int t = threadIdx.x;
    if (t < 2 * D_) {
        int r = t / D_, o = t - r * D_;
        const float* z = g_z + r * 1328;
        float acc = fc1b[o];
        for (int i = 0; i < 1328; i++) acc += z[i] * fc1W[i * D_ + o];
        a1[r][o] = acc;
    }
    __syncthreads();
    if (t < D_) {
        float m = (a1[0][t] + a1[1][t]) * 0.5f;
        float d0 = a1[0][t] - m, d1 = a1[1][t] - m;
        float var = (d0 * d0 + d1 * d1) * 0.5f;
        float is = rsqrtf(var + 1e-5f);
        a1[0][t] = fmaxf(d0 * is * bn1g[t] + bn1b[t], 0.f);
        a1[1][t] = fmaxf(d1 * is * bn1g[t] + bn1b[t], 0.f);
    }
    __syncthreads();
    if (t < 2 * D3_) {
        int r = t / D3_, o = t - r * D3_;
        float acc = fc2b[o];
        for (int i = 0; i < D_; i++) acc += a1[r][i] * fc2W[i * D3_ + o];
        a2[r][o] = acc;
    }
    __syncthreads();
    if (t < D3_) {
        float m = (a2[0][t] + a2[1][t]) * 0.5f;
        float d0 = a2[0][t] - m, d1 = a2[1][t] - m;
        float var = (d0 * d0 + d1 * d1) * 0.5f;
        float is = rsqrtf(var + 1e-5f);
        a2[0][t] = fmaxf(d0 * is * bn2g[t] + bn2b[t], 0.f);
        a2[1][t] = fmaxf(d1 * is * bn2g[t] + bn2b[t], 0.f);
    }
    __syncthreads();
    if (t < 4) {
        int r = t >> 1, o = t & 1;
        float acc = fc3b[o];
        for (int i = 0; i < D3_; i++) acc += a2[r][i] * fc3W[i * 2 + o];
        out[r * 2 + o] = acc;
    }
}

extern "C" void kernel_launch(void* const* d_in, const int* in_sizes, int n_in,
                              void* d_out, int out_size) {
    const float* x    = (const float*)d_in[0];
    const int*   ei   = (const int*)d_in[1];
    const float* eat  = (const float*)d_in[3];
    const float* pos  = (const float*)d_in[4];
    const float* c1W1 = (const float*)d_in[6];
    const float* c1W2 = (const float*)d_in[7];
    const float* c1nb = (const float*)d_in[8];
    const float* c1b  = (const float*)d_in[9];
    const float* p1w  = (const float*)d_in[10];
    const float* c2W1 = (const float*)d_in[11];
    const float* c2W2 = (const float*)d_in[12];
    const float* c2nb = (const float*)d_in[13];
    const float* c2b  = (const float*)d_in[14];
    const float* p2w  = (const float*)d_in[15];
    const float* fc1W = (const float*)d_in[16];
    const float* fc1b = (const float*)d_in[17];
    const float* bn1g = (const float*)d_in[18];
    const float* bn1b = (const float*)d_in[19];
    const float* fc2W = (const float*)d_in[20];
    const float* fc2b = (const float*)d_in[21];
    const float* bn2g = (const float*)d_in[22];
    const float* bn2b = (const float*)d_in[23];
    const float* fc3W = (const float*)d_in[24];
    const float* fc3b = (const float*)d_in[25];
    const int* src = ei;
    const int* dst = ei + NE_;
    float* out = (float*)d_out;

    k_zero<<<3, 256>>>();

    // stage 1: conv1
    k_gates<<<(NN_ * 32 + 255) / 256, 256>>>(pos, c1W1, NN_, 0);
    k_expand<<<NN_, 256>>>(x, NN_, 0);
    k_gemm<<<dim3((D_ + BN - 1) / BN, (NN_ + BM - 1) / BM, SPLITK), 256>>>(c1W2, c1nb, NN_);
    k_reduce<<<(NN_ * D_ + 255) / 256, 256>>>(NN_);
    k_count1<<<(NE_ + 255) / 256, 256>>>(dst);
    k_scan<<<1, 1024>>>(0);
    k_scatter1<<<(NE_ + 255) / 256, 256>>>(dst);
    k_agg<<<NN_, 256>>>(eat, src, c1b, NN_, 0);

    // pool1 + readout1
    k_score<<<(NN_ * 32 + 255) / 256, 256>>>(p1w, NN_);
    k_select<<<G_, NP_>>>(NP_, K1_, 0);
    k_gather<<<G_ * K1_, 256>>>(0);
    k_readout<<<G_, D_>>>(K1_, 1.f / (float)K1_, 0, 0);

    // stage 2: conv2
    k_gates<<<(NP_ * 32 + 255) / 256, 256>>>(pos, c2W1, NP_, 1);
    k_expand<<<NP_, 256>>>(nullptr, NP_, 1);
    k_gemm<<<dim3((D_ + BN - 1) / BN, (NP_ + BM - 1) / BM, SPLITK), 256>>>(c2W2, c2nb, NP_);
    k_reduce<<<(NP_ * D_ + 255) / 256, 256>>>(NP_);
    k_count2<<<(NE_ + 255) / 256, 256>>>(src, dst);
    k_scan<<<1, 1024>>>(1);
    k_scatter2<<<(NE_ + 255) / 256, 256>>>(src, dst);
    k_agg<<<NP_, 256>>>(eat, src, c2b, NP_, 1);

    // pool2 + readout2
    k_score<<<(NP_ * 32 + 255) / 256, 256>>>(p2w, NP_);
    k_select<<<G_, K1_>>>(K1_, K2_, 1);
    k_gather<<<G_ * K2_, 256>>>(1);
    k_readout<<<G_, D_>>>(K2_, 1.f / (float)K2_, 664, 1);

    // MLP head
    k_head<<<1, 704>>>(fc1W, fc1b, bn1g, bn1b, fc2W, fc2b, bn2g, bn2b, fc3W, fc3b, out);
}

// round 4
// speedup vs baseline: 1.4601x; 1.4601x over previous
#include <cuda_runtime.h>
#include <math.h>

#define G_    2
#define NP_   332
#define NN_   664
#define NE_   21248
#define D_    332
#define KH_   6
#define K1_   166
#define K2_   83
#define KCAT_ 2324
#define D3_   128
#define MAXDEG 352
#define SK    16      /* split-K factor */
#define KSPL  160     /* per-split K range, multiple of BK=16: 16*ceil(2324/256) */

// ---------------- static device scratch ----------------
__device__ float g_A[(size_t)NN_ * KCAT_];
__device__ float g_part[SK][NN_ * D_];
__device__ float g_xt[NN_ * D_];
__device__ float g_conv[NN_ * D_];
__device__ float g_score[NN_];
__device__ float g_hp[NP_ * D_];
__device__ float g_z[G_ * 1328];
__device__ int   g_perm1[G_ * K1_];
__device__ int   g_perm2[G_ * K2_];
__device__ int   g_newidx[NN_];
__device__ int   g_off[NN_ + 1];
__device__ int   g_off2[NP_ + 1];
__device__ int   g_el[NE_], g_el2[NE_];

// ---------------- CSR build: count + scan + scatter in ONE block ----------------
__global__ void k_csr(const int* __restrict__ src, const int* __restrict__ dst, int stage) {
    __shared__ int cnt[NN_];
    __shared__ int offs[NN_ + 1];
    __shared__ int s[1024];
    int n = stage ? NP_ : NN_;
    int t = threadIdx.x;
    for (int i = t; i < n; i += 1024) cnt[i] = 0;
    __syncthreads();
    for (int e = t; e < NE_; e += 1024) {
        if (stage == 0) {
            atomicAdd(&cnt[dst[e]], 1);
        } else {
            int ns = g_newidx[src[e]], nd = g_newidx[dst[e]];
            if (ns >= 0 && nd >= 0) atomicAdd(&cnt[nd], 1);
        }
    }
    __syncthreads();
    s[t] = (t < n) ? cnt[t] : 0;
    __syncthreads();
    for (int d = 1; d < 1024; d <<= 1) {
        int u = (t >= d) ? s[t - d] : 0;
        __syncthreads();
        s[t] += u;
        __syncthreads();
    }
    if (t < n) offs[t + 1] = s[t];
    if (t == 0) offs[0] = 0;
    __syncthreads();
    // publish offsets for k_agg
    int* goff = stage ? g_off2 : g_off;
    for (int i = t; i <= n; i += 1024) goff[i] = offs[i];
    // reset cursors
    for (int i = t; i < n; i += 1024) cnt[i] = 0;
    __syncthreads();
    for (int e = t; e < NE_; e += 1024) {
        if (stage == 0) {
            int d = dst[e];
            int p = atomicAdd(&cnt[d], 1);
            g_el[offs[d] + p] = e;
        } else {
            int ns = g_newidx[src[e]], nd = g_newidx[dst[e]];
            if (ns >= 0 && nd >= 0) {
                int p = atomicAdd(&cnt[nd], 1);
                g_el2[offs[nd] + p] = e;
            }
        }
    }
}

// ---------------- fused gate-MLP + Kronecker expand ----------------
// h[r,k] = relu(pos[row]@W1)[k], h[6]=1 ; A'[r, k*332+i] = h[k]*x[r,i]
__global__ void k_gates_expand(const float* __restrict__ pos, const float* __restrict__ W1,
                               const float* __restrict__ xin, int usePerm) {
    int r = blockIdx.x;
    __shared__ float h[8];
    __shared__ float xs[D_];
    int tid = threadIdx.x;
    int row = usePerm ? g_perm1[r] : r;
    if (tid < 32) {
        const float* p = pos + (size_t)row * D_;
        float acc[KH_];
#pragma unroll
        for (int k = 0; k < KH_; k++) acc[k] = 0.f;
        for (int i = tid; i < D_; i += 32) {
            float pv = p[i];
#pragma unroll
            for (int k = 0; k < KH_; k++) acc[k] += pv * W1[i * KH_ + k];
        }
#pragma unroll
        for (int k = 0; k < KH_; k++)
#pragma unroll
            for (int o = 16; o; o >>= 1) acc[k] += __shfl_xor_sync(0xffffffffu, acc[k], o);
        if (tid == 0) {
#pragma unroll
            for (int k = 0; k < KH_; k++) h[k] = fmaxf(acc[k], 0.f);
            h[KH_] = 1.f;
        }
    }
    const float* x = usePerm ? (g_hp + (size_t)r * D_) : (xin + (size_t)r * D_);
    for (int i = tid; i < D_ / 4; i += blockDim.x)
        ((float4*)xs)[i] = ((const float4*)x)[i];
    __syncthreads();
    float4* out = (float4*)(g_A + (size_t)r * KCAT_);
    for (int c4 = tid; c4 < KCAT_ / 4; c4 += blockDim.x) {
        int c = c4 * 4;
        int k = c / D_, i = c - k * D_;
        float hv = h[k];
        float4 xv = *(const float4*)&xs[i];
        out[c4] = make_float4(hv * xv.x, hv * xv.y, hv * xv.z, hv * xv.w);
    }
}

// ---------------- split-K GEMM: g_part[z] = A'[:,ks] @ B[ks,:] ----------------
// 128 threads, BM=64 BN=64 BK=16, 8x4 per thread, double-buffered smem, float4 IO
__global__ void __launch_bounds__(128) k_gemm(const float* __restrict__ W2,
                                              const float* __restrict__ nb, int M) {
    __shared__ float As[2][16][64];
    __shared__ float Bs[2][16][64];
    int bn = blockIdx.x * 64, bm = blockIdx.y * 64, z = blockIdx.z;
    int k_begin = z * KSPL;
    int k_end = min(KCAT_, k_begin + KSPL);
    int tid = threadIdx.x;
    int ty = tid >> 4, tx = tid & 15;          // ty 0..7 (rows*8), tx 0..15 (cols*4)
    float acc[8][4];
#pragma unroll
    for (int i = 0; i < 8; i++)
#pragma unroll
        for (int j = 0; j < 4; j++) acc[i][j] = 0.f;

    int nt = (k_end > k_begin) ? ((k_end - k_begin + 15) >> 4) : 0;
    float4 ra[2], rb[2];

#define LOAD_TILE(K0)                                                              \
    {                                                                              \
        _Pragma("unroll") for (int i = 0; i < 2; i++) {                            \
            int idx = tid * 2 + i;                                                 \
            int row = idx >> 2, k4 = idx & 3;                                      \
            int m = bm + row, k = (K0) + k4 * 4;                                   \
            float4 v = make_float4(0.f, 0.f, 0.f, 0.f);                            \
            if (m < M && k < k_end) v = *(const float4*)&g_A[(size_t)m * KCAT_ + k]; \
            ra[i] = v;                                                             \
        }                                                                          \
        _Pragma("unroll") for (int i = 0; i < 2; i++) {                            \
            int idx = tid * 2 + i;                                                 \
            int kl = idx >> 4, j4 = idx & 15;                                      \
            int k = (K0) + kl, o = bn + j4 * 4;                                    \
            float4 v = make_float4(0.f, 0.f, 0.f, 0.f);                            \
            if (k < k_end && o < D_) {                                             \
                const float* Brow = (k < KH_ * D_) ? (W2 + (size_t)k * D_)         \
                                                   : (nb + (size_t)(k - KH_ * D_) * D_); \
                v = *(const float4*)&Brow[o];                                      \
            }                                                                      \
            rb[i] = v;                                                             \
        }                                                                          \
    }

#define STORE_TILE(B)                                                              \
    {                                                                              \
        _Pragma("unroll") for (int i = 0; i < 2; i++) {                            \
            int idx = tid * 2 + i;                                                 \
            int row = idx >> 2, k4 = idx & 3;                                      \
            As[B][k4 * 4 + 0][row] = ra[i].x;                                      \
            As[B][k4 * 4 + 1][row] = ra[i].y;                                      \
            As[B][k4 * 4 + 2][row] = ra[i].z;                                      \
            As[B][k4 * 4 + 3][row] = ra[i].w;                                      \
            int kl = idx >> 4, j4 = idx & 15;                                      \
            *(float4*)&Bs[B][kl][j4 * 4] = rb[i];                                  \
        }                                                                          \
    }

    int buf = 0;
    if (nt > 0) {
        LOAD_TILE(k_begin);
        STORE_TILE(0);
    }
    __syncthreads();
    for (int t = 0; t < nt; t++) {
        if (t + 1 < nt) LOAD_TILE(k_begin + (t + 1) * 16);
#pragma unroll
        for (int kk = 0; kk < 16; kk++) {
            float a[8], b[4];
            *(float4*)&a[0] = *(const float4*)&As[buf][kk][ty * 8];
            *(float4*)&a[4] = *(const float4*)&As[buf][kk][ty * 8 + 4];
            *(float4*)&b[0] = *(const float4*)&Bs[buf][kk][tx * 4];
#pragma unroll
            for (int i = 0; i < 8; i++)
#pragma unroll
                for (int j = 0; j < 4; j++) acc[i][j] += a[i] * b[j];
        }
        if (t + 1 < nt) {
            __syncthreads();
            STORE_TILE(buf ^ 1);
            __syncthreads();
            buf ^= 1;
        }
    }
#pragma unroll
    for (int i = 0; i < 8; i++) {
        int m = bm + ty * 8 + i;
        int o = bn + tx * 4;
        if (m < M && o < D_)
            *(float4*)&g_part[z][m * D_ + o] =
                make_float4(acc[i][0], acc[i][1], acc[i][2], acc[i][3]);
    }
#undef LOAD_TILE
#undef STORE_TILE
}

__global__ void k_reduce(int M) {
    int t = blockIdx.x * blockDim.x + threadIdx.x;
    int n4 = M * (D_ / 4);
    if (t < n4) {
        float4 s = make_float4(0.f, 0.f, 0.f, 0.f);
#pragma unroll
        for (int z = 0; z < SK; z++) {
            float4 v = ((const float4*)g_part[z])[t];
            s.x += v.x; s.y += v.y; s.z += v.z; s.w += v.w;
        }
        ((float4*)g_xt)[t] = s;
    }
}

// ---------------- per-dst softmax aggregation ----------------
__global__ void k_agg(const float* __restrict__ attr, const int* __restrict__ src,
                      const float* __restrict__ bias, int n, int stage) {
    int d = blockIdx.x;
    if (d >= n) return;
    const int* off = stage ? g_off2 : g_off;
    const int* el = stage ? g_el2 : g_el;
    int s0 = off[d], cnt = off[d + 1] - s0;
    __shared__ float w[MAXDEG];
    __shared__ int sn[MAXDEG];
    __shared__ float sh_wself, sh_inv;
    int tid = threadIdx.x;
    for (int i = tid; i < cnt; i += blockDim.x) {
        int e = el[s0 + i];
        w[i] = attr[e];
        int s = src[e];
        sn[i] = stage ? g_newidx[s] : s;
    }
    __syncthreads();
    if (tid < 32) {
        float mx = 1.0f;
        for (int i = tid; i < cnt; i += 32) mx = fmaxf(mx, w[i]);
#pragma unroll
        for (int o = 16; o; o >>= 1) mx = fmaxf(mx, __shfl_xor_sync(0xffffffffu, mx, o));
        float sm = (tid == 0) ? __expf(1.f - mx) : 0.f;
        for (int i = tid; i < cnt; i += 32) {
            float e_ = __expf(w[i] - mx);
            w[i] = e_;
            sm += e_;
        }
#pragma unroll
        for (int o = 16; o; o >>= 1) sm += __shfl_xor_sync(0xffffffffu, sm, o);
        if (tid == 0) {
            float inv = 1.f / sm;
            sh_inv = inv;
            sh_wself = __expf(1.f - mx) * inv;
        }
    }
    __syncthreads();
    float wself = sh_wself, inv = sh_inv;
    for (int o = tid; o < D_; o += blockDim.x) {
        float acc = 0.f;
        for (int i = 0; i < cnt; i++) acc += w[i] * g_xt[(size_t)sn[i] * D_ + o];
        g_conv[(size_t)d * D_ + o] = acc * inv + wself * g_xt[(size_t)d * D_ + o] + bias[o];
    }
}

// ---------------- fused score + rank-based top-k select ----------------
__global__ void k_score_select(const float* __restrict__ pw, int nper, int k, int stage) {
    int gi = blockIdx.x;
    __shared__ float sc[NP_];
    int tid = threadIdx.x;         // 512
    int w = tid >> 5, lane = tid & 31;
    for (int nl = w; nl < nper; nl += 16) {
        int node = gi * nper + nl;
        float nrm = 0.f, dot = 0.f;
        for (int i = lane; i < D_; i += 32) {
            float wv = pw[i];
            nrm += wv * wv;
            dot += g_conv[(size_t)node * D_ + i] * wv;
        }
#pragma unroll
        for (int o = 16; o; o >>= 1) {
            nrm += __shfl_xor_sync(0xffffffffu, nrm, o);
            dot += __shfl_xor_sync(0xffffffffu, dot, o);
        }
        if (lane == 0) {
            float v = dot * rsqrtf(nrm);
            float s_ = 1.f / (1.f + __expf(-v));
            sc[nl] = s_;
            g_score[node] = s_;
        }
    }
    __syncthreads();
    if (tid < nper) {
        float mine = sc[tid];
        int rank = 0;
        for (int j = 0; j < nper; j++) {
            float sj = sc[j];
            rank += (sj > mine) || (sj == mine && j < tid);
        }
        int node = gi * nper + tid;
        if (stage == 0) {
            g_newidx[node] = (rank < k) ? gi * k + rank : -1;
            if (rank < k) g_perm1[gi * k + rank] = node;
        } else {
            if (rank < k) g_perm2[gi * k + rank] = node;
        }
    }
}

// ---------------- fused gather(*score) + readout (max||mean) ----------------
__global__ void k_gather_readout(int kk, float inv, int zoff, int stage) {
    int gi = blockIdx.x;
    __shared__ int pm[K1_];
    __shared__ float ss[K1_];
    int tid = threadIdx.x;
    for (int j = tid; j < kk; j += blockDim.x) {
        int old = stage ? g_perm2[gi * kk + j] : g_perm1[gi * kk + j];
        pm[j] = old;
        ss[j] = g_score[old];
    }
    __syncthreads();
    int o = tid;
    if (o < D_) {
        float mx = -3.4e38f, sm = 0.f;
        for (int j = 0; j < kk; j++) {
            float v = g_conv[(size_t)pm[j] * D_ + o] * ss[j];
            if (stage == 0) g_hp[(size_t)(gi * kk + j) * D_ + o] = v;
            mx = fmaxf(mx, v);
            sm += v;
        }
        g_z[gi * 1328 + zoff + o] = mx;
        g_z[gi * 1328 + zoff + D_ + o] = sm * inv;
    }
}

// ---------------- MLP head ----------------
__global__ void k_head(const float* __restrict__ fc1W, const float* __restrict__ fc1b,
                       const float* __restrict__ bn1g, const float* __restrict__ bn1b,
                       const float* __restrict__ fc2W, const float* __restrict__ fc2b,
                       const float* __restrict__ bn2g, const float* __restrict__ bn2b,
                       const float* __restrict__ fc3W, const float* __restrict__ fc3b,
                       float* __restrict__ out) {
    __shared__ float a1[2][D_];
    __shared__ float a2[2][D3_];
    int t = threadIdx.x;
    if (t < 2 * D_) {
        int r = t / D_, o = t - r * D_;
        const float* z = g_z + r * 1328;
        float acc = fc1b[o];
        for (int i = 0; i < 1328; i++) acc += z[i] * fc1W[i * D_ + o];
        a1[r][o] = acc;
    }
    __syncthreads();
    if (t < D_) {
        float m = (a1[0][t] + a1[1][t]) * 0.5f;
        float d0 = a1[0][t] - m, d1 = a1[1][t] - m;
        float var = (d0 * d0 + d1 * d1) * 0.5f;
        float is = rsqrtf(var + 1e-5f);
        a1[0][t] = fmaxf(d0 * is * bn1g[t] + bn1b[t], 0.f);
        a1[1][t] = fmaxf(d1 * is * bn1g[t] + bn1b[t], 0.f);
    }
    __syncthreads();
    if (t < 2 * D3_) {
        int r = t / D3_, o = t - r * D3_;
        float acc = fc2b[o];
        for (int i = 0; i < D_; i++) acc += a1[r][i] * fc2W[i * D3_ + o];
        a2[r][o] = acc;
    }
    __syncthreads();
    if (t < D3_) {
        float m = (a2[0][t] + a2[1][t]) * 0.5f;
        float d0 = a2[0][t] - m, d1 = a2[1][t] - m;
        float var = (d0 * d0 + d1 * d1) * 0.5f;
        float is = rsqrtf(var + 1e-5f);
        a2[0][t] = fmaxf(d0 * is * bn2g[t] + bn2b[t], 0.f);
        a2[1][t] = fmaxf(d1 * is * bn2g[t] + bn2b[t], 0.f);
    }
    __syncthreads();
    if (t < 4) {
        int r = t >> 1, o = t & 1;
        float acc = fc3b[o];
        for (int i = 0; i < D3_; i++) acc += a2[r][i] * fc3W[i * 2 + o];
        out[r * 2 + o] = acc;
    }
}

extern "C" void kernel_launch(void* const* d_in, const int* in_sizes, int n_in,
                              void* d_out, int out_size) {
    const float* x    = (const float*)d_in[0];
    const int*   ei   = (const int*)d_in[1];
    const float* eat  = (const float*)d_in[3];
    const float* pos  = (const float*)d_in[4];
    const float* c1W1 = (const float*)d_in[6];
    const float* c1W2 = (const float*)d_in[7];
    const float* c1nb = (const float*)d_in[8];
    const float* c1b  = (const float*)d_in[9];
    const float* p1w  = (const float*)d_in[10];
    const float* c2W1 = (const float*)d_in[11];
    const float* c2W2 = (const float*)d_in[12];
    const float* c2nb = (const float*)d_in[13];
    const float* c2b  = (const float*)d_in[14];
    const float* p2w  = (const float*)d_in[15];
    const float* fc1W = (const float*)d_in[16];
    const float* fc1b = (const float*)d_in[17];
    const float* bn1g = (const float*)d_in[18];
    const float* bn1b = (const float*)d_in[19];
    const float* fc2W = (const float*)d_in[20];
    const float* fc2b = (const float*)d_in[21];
    const float* bn2g = (const float*)d_in[22];
    const float* bn2b = (const float*)d_in[23];
    const float* fc3W = (const float*)d_in[24];
    const float* fc3b = (const float*)d_in[25];
    const int* src = ei;
    const int* dst = ei + NE_;
    float* out = (float*)d_out;

    // stage 1: conv1
    k_csr<<<1, 1024>>>(src, dst, 0);
    k_gates_expand<<<NN_, 256>>>(pos, c1W1, x, 0);
    k_gemm<<<dim3((D_ + 63) / 64, (NN_ + 63) / 64, SK), 128>>>(c1W2, c1nb, NN_);
    k_reduce<<<(NN_ * (D_ / 4) + 255) / 256, 256>>>(NN_);
    k_agg<<<NN_, 256>>>(eat, src, c1b, NN_, 0);

    // pool1 + readout1
    k_score_select<<<G_, 512>>>(p1w, NP_, K1_, 0);
    k_gather_readout<<<G_, 352>>>(K1_, 1.f / (float)K1_, 0, 0);

    // stage 2: conv2
    k_csr<<<1, 1024>>>(src, dst, 1);
    k_gates_expand<<<NP_, 256>>>(pos, c2W1, nullptr, 1);
    k_gemm<<<dim3((D_ + 63) / 64, (NP_ + 63) / 64, SK), 128>>>(c2W2, c2nb, NP_);
    k_reduce<<<(NP_ * (D_ / 4) + 255) / 256, 256>>>(NP_);
    k_agg<<<NP_, 256>>>(eat, src, c2b, NP_, 1);

    // pool2 + readout2
    k_score_select<<<G_, 512>>>(p2w, K1_, K2_, 1);
    k_gather_readout<<<G_, 352>>>(K2_, 1.f / (float)K2_, 2 * D_, 1);

    // MLP head
    k_head<<<1, 704>>>(fc1W, fc1b, bn1g, bn1b, fc2W, fc2b, bn2g, bn2b, fc3W, fc3b, out);
}

// round 6
// speedup vs baseline: 1.5321x; 1.0494x over previous
#include <cuda_runtime.h>
#include <math.h>

#define G_    2
#define NP_   332
#define NN_   664
#define NE_   21248
#define EPG_  (NE_ / G_)        /* 10624 edges per graph */
#define D_    332
#define KH_   6
#define K1_   166
#define K2_   83
#define KCAT_ 2324
#define D3_   128
#define MAXDEG 352
#define SK    8
#define KSPL  304               /* 8*304=2432 >= 2324, multiple of 16 */

typedef unsigned long long u64;
typedef unsigned int u32;

// ---------------- static device scratch ----------------
__device__ float g_A[(size_t)NN_ * KCAT_];
__device__ float g_part[SK][NN_ * D_];
__device__ float g_xt[NN_ * D_];
__device__ float g_conv[NN_ * D_];
__device__ float g_hp[NP_ * D_];
__device__ float g_z[G_ * 1328];
__device__ int   g_perm1[G_ * K1_];
__device__ int   g_newidx[NN_];
__device__ int   g_off[NN_ + 1];
__device__ int   g_off2[NP_];
__device__ int   g_deg2[NP_];
__device__ int   g_el[NE_], g_el2[NE_];

__device__ __forceinline__ u64 pack2(float v) {
    u32 b = __float_as_uint(v);
    return ((u64)b << 32) | (u64)b;
}
__device__ __forceinline__ void ffma2(u64& d, u64 a, u64 b) {
    asm("fma.rn.f32x2 %0, %1, %2, %0;" : "+l"(d) : "l"(a), "l"(b));
}

// ---------------- stage-1 CSR build (count + scan + scatter, one block) ----------------
__global__ void k_csr(const int* __restrict__ dst) {
    __shared__ int cnt[NN_];
    __shared__ int offs[NN_ + 1];
    __shared__ int s[1024];
    int t = threadIdx.x;
    for (int i = t; i < NN_; i += 1024) cnt[i] = 0;
    __syncthreads();
    for (int e = t; e < NE_; e += 1024) atomicAdd(&cnt[dst[e]], 1);
    __syncthreads();
    s[t] = (t < NN_) ? cnt[t] : 0;
    __syncthreads();
    for (int d = 1; d < 1024; d <<= 1) {
        int u = (t >= d) ? s[t - d] : 0;
        __syncthreads();
        s[t] += u;
        __syncthreads();
    }
    if (t < NN_) offs[t + 1] = s[t];
    if (t == 0) offs[0] = 0;
    __syncthreads();
    for (int i = t; i <= NN_; i += 1024) g_off[i] = offs[i];
    for (int i = t; i < NN_; i += 1024) cnt[i] = 0;
    __syncthreads();
    for (int e = t; e < NE_; e += 1024) {
        int d = dst[e];
        int p = atomicAdd(&cnt[d], 1);
        g_el[offs[d] + p] = e;
    }
}

// ---------------- fused gate-MLP + Kronecker expand ----------------
__global__ void k_gates_expand(const float* __restrict__ pos, const float* __restrict__ W1,
                               const float* __restrict__ xin, int usePerm) {
    int r = blockIdx.x;
    __shared__ float h[8];
    __shared__ float xs[D_];
    int tid = threadIdx.x;
    int row = usePerm ? g_perm1[r] : r;
    if (tid < 32) {
        const float* p = pos + (size_t)row * D_;
        float acc[KH_];
#pragma unroll
        for (int k = 0; k < KH_; k++) acc[k] = 0.f;
        for (int i = tid; i < D_; i += 32) {
            float pv = p[i];
#pragma unroll
            for (int k = 0; k < KH_; k++) acc[k] += pv * W1[i * KH_ + k];
        }
#pragma unroll
        for (int k = 0; k < KH_; k++)
#pragma unroll
            for (int o = 16; o; o >>= 1) acc[k] += __shfl_xor_sync(0xffffffffu, acc[k], o);
        if (tid == 0) {
#pragma unroll
            for (int k = 0; k < KH_; k++) h[k] = fmaxf(acc[k], 0.f);
            h[KH_] = 1.f;
        }
    }
    const float* x = usePerm ? (g_hp + (size_t)r * D_) : (xin + (size_t)r * D_);
    for (int i = tid; i < D_ / 4; i += blockDim.x)
        ((float4*)xs)[i] = ((const float4*)x)[i];
    __syncthreads();
    float4* out = (float4*)(g_A + (size_t)r * KCAT_);
    for (int c4 = tid; c4 < KCAT_ / 4; c4 += blockDim.x) {
        int c = c4 * 4;
        int k = c / D_, i = c - k * D_;
        float hv = h[k];
        float4 xv = *(const float4*)&xs[i];
        out[c4] = make_float4(hv * xv.x, hv * xv.y, hv * xv.z, hv * xv.w);
    }
}

// ---------------- split-K GEMM with packed f32x2 FMA ----------------
// 128 threads, BM=64 BN=64 BK=16, 8x4 outputs/thread via 16 FFMA2 per k-step.
// A smem stores duplicated pairs (a,a); B smem plain floats (natural pairs).
__global__ void __launch_bounds__(128) k_gemm(const float* __restrict__ W2,
                                              const float* __restrict__ nb, int M) {
    __shared__ u64   As2[2][16][64];       // (a,a) pairs           16KB
    __shared__ float Bs[2][16][64];        //                        8KB
    int bn = blockIdx.x * 64, bm = blockIdx.y * 64, z = blockIdx.z;
    int k_begin = z * KSPL;
    int k_end = min(KCAT_, k_begin + KSPL);
    int tid = threadIdx.x;
    int ty = tid >> 4, tx = tid & 15;
    u64 acc2[8][2];
#pragma unroll
    for (int i = 0; i < 8; i++) { acc2[i][0] = 0ull; acc2[i][1] = 0ull; }

    int nt = (k_end > k_begin) ? ((k_end - k_begin + 15) >> 4) : 0;
    float4 ra[2], rb[2];

#define LOAD_TILE(K0)                                                                \
    {                                                                                \
        _Pragma("unroll") for (int i = 0; i < 2; i++) {                              \
            int idx = tid * 2 + i;                                                   \
            int row = idx >> 2, k4 = idx & 3;                                        \
            int m = bm + row, k = (K0) + k4 * 4;                                     \
            float4 v = make_float4(0.f, 0.f, 0.f, 0.f);                              \
            if (m < M && k < k_end) v = *(const float4*)&g_A[(size_t)m * KCAT_ + k]; \
            ra[i] = v;                                                               \
        }                                                                            \
        _Pragma("unroll") for (int i = 0; i < 2; i++) {                              \
            int idx = tid * 2 + i;                                                   \
            int kl = idx >> 4, j4 = idx & 15;                                        \
            int k = (K0) + kl, o = bn + j4 * 4;                                      \
            float4 v = make_float4(0.f, 0.f, 0.f, 0.f);                              \
            if (k < k_end && o < D_) {                                               \
                const float* Brow = (k < KH_ * D_) ? (W2 + (size_t)k * D_)           \
                                                   : (nb + (size_t)(k - KH_ * D_) * D_); \
                v = *(const float4*)&Brow[o];                                        \
            }                                                                        \
            rb[i] = v;                                                               \
        }                                                                            \
    }

#define STORE_TILE(B)                                                                \
    {                                                                                \
        _Pragma("unroll") for (int i = 0; i < 2; i++) {                              \
            int idx = tid * 2 + i;                                                   \
            int row = idx >> 2, k4 = idx & 3;                                        \
            As2[B][k4 * 4 + 0][row] = pack2(ra[i].x);                                \
            As2[B][k4 * 4 + 1][row] = pack2(ra[i].y);                                \
            As2[B][k4 * 4 + 2][row] = pack2(ra[i].z);                                \
            As2[B][k4 * 4 + 3][row] = pack2(ra[i].w);                                \
            int kl = idx >> 4, j4 = idx & 15;                                        \
            *(float4*)&Bs[B][kl][j4 * 4] = rb[i];                                    \
        }                                                                            \
    }

    int buf = 0;
    if (nt > 0) {
        LOAD_TILE(k_begin);
        STORE_TILE(0);
    }
    __syncthreads();
    for (int t = 0; t < nt; t++) {
        if (t + 1 < nt) LOAD_TILE(k_begin + (t + 1) * 16);
#pragma unroll
        for (int kk = 0; kk < 16; kk++) {
            u64 a2[8];
            const ulonglong2* pa = (const ulonglong2*)&As2[buf][kk][ty * 8];
#pragma unroll
            for (int q = 0; q < 4; q++) {
                ulonglong2 v = pa[q];
                a2[q * 2] = v.x;
                a2[q * 2 + 1] = v.y;
            }
            ulonglong2 qb = *(const ulonglong2*)&Bs[buf][kk][tx * 4];
            u64 b01 = qb.x, b23 = qb.y;
#pragma unroll
            for (int i = 0; i < 8; i++) {
                ffma2(acc2[i][0], a2[i], b01);
                ffma2(acc2[i][1], a2[i], b23);
            }
        }
        if (t + 1 < nt) {
            __syncthreads();
            STORE_TILE(buf ^ 1);
            __syncthreads();
            buf ^= 1;
        }
    }
#pragma unroll
    for (int i = 0; i < 8; i++) {
        int m = bm + ty * 8 + i;
        int o = bn + tx * 4;
        if (m < M && o < D_) {
            float4 r;
            r.x = __uint_as_float((u32)acc2[i][0]);
            r.y = __uint_as_float((u32)(acc2[i][0] >> 32));
            r.z = __uint_as_float((u32)acc2[i][1]);
            r.w = __uint_as_float((u32)(acc2[i][1] >> 32));
            *(float4*)&g_part[z][m * D_ + o] = r;
        }
    }
#undef LOAD_TILE
#undef STORE_TILE
}

__global__ void k_reduce(int M) {
    int t = blockIdx.x * blockDim.x + threadIdx.x;
    int n4 = M * (D_ / 4);
    if (t < n4) {
        float4 s = make_float4(0.f, 0.f, 0.f, 0.f);
#pragma unroll
        for (int z = 0; z < SK; z++) {
            float4 v = ((const float4*)g_part[z])[t];
            s.x += v.x; s.y += v.y; s.z += v.z; s.w += v.w;
        }
        ((float4*)g_xt)[t] = s;
    }
}

// ---------------- per-dst softmax aggregation ----------------
__global__ void k_agg(const float* __restrict__ attr, const int* __restrict__ src,
                      const float* __restrict__ bias, int n, int stage) {
    int d = blockIdx.x;
    if (d >= n) return;
    int s0, cnt;
    if (stage) { s0 = g_off2[d]; cnt = g_deg2[d]; }
    else       { s0 = g_off[d];  cnt = g_off[d + 1] - s0; }
    __shared__ float w[MAXDEG];
    __shared__ int sn[MAXDEG];
    __shared__ float sh_wself, sh_inv;
    int tid = threadIdx.x;
    const int* el = stage ? g_el2 : g_el;
    for (int i = tid; i < cnt; i += blockDim.x) {
        int e = el[s0 + i];
        w[i] = attr[e];
        int s = src[e];
        sn[i] = stage ? g_newidx[s] : s;
    }
    __syncthreads();
    if (tid < 32) {
        float mx = 1.0f;
        for (int i = tid; i < cnt; i += 32) mx = fmaxf(mx, w[i]);
#pragma unroll
        for (int o = 16; o; o >>= 1) mx = fmaxf(mx, __shfl_xor_sync(0xffffffffu, mx, o));
        float sm = (tid == 0) ? __expf(1.f - mx) : 0.f;
        for (int i = tid; i < cnt; i += 32) {
            float e_ = __expf(w[i] - mx);
            w[i] = e_;
            sm += e_;
        }
#pragma unroll
        for (int o = 16; o; o >>= 1) sm += __shfl_xor_sync(0xffffffffu, sm, o);
        if (tid == 0) {
            float inv = 1.f / sm;
            sh_inv = inv;
            sh_wself = __expf(1.f - mx) * inv;
        }
    }
    __syncthreads();
    float wself = sh_wself, inv = sh_inv;
    for (int o = tid; o < D_; o += blockDim.x) {
        float acc = 0.f;
        for (int i = 0; i < cnt; i++) acc += w[i] * g_xt[(size_t)sn[i] * D_ + o];
        g_conv[(size_t)d * D_ + o] = acc * inv + wself * g_xt[(size_t)d * D_ + o] + bias[o];
    }
}

// ---------------- fused pool: score + rank-topk + (stage0: CSR2) + gather + readout ----------------
__global__ void k_pool(const float* __restrict__ pw, const int* __restrict__ src,
                       const int* __restrict__ dst, int nper, int k, int stage,
                       int zoff, float inv) {
    int gi = blockIdx.x;
    __shared__ float sc[NP_];
    __shared__ int pm[K1_];
    __shared__ float ss[K1_];
    __shared__ int cnt[K1_];
    __shared__ int offs[K1_ + 1];
    __shared__ int s[512];
    int tid = threadIdx.x;         // 512
    int w = tid >> 5, lane = tid & 31;
    // A: scores
    for (int nl = w; nl < nper; nl += 16) {
        int node = gi * nper + nl;
        float nrm = 0.f, dot = 0.f;
        for (int i = lane; i < D_; i += 32) {
            float wv = pw[i];
            nrm += wv * wv;
            dot += g_conv[(size_t)node * D_ + i] * wv;
        }
#pragma unroll
        for (int o = 16; o; o >>= 1) {
            nrm += __shfl_xor_sync(0xffffffffu, nrm, o);
            dot += __shfl_xor_sync(0xffffffffu, dot, o);
        }
        if (lane == 0) {
            float v = dot * rsqrtf(nrm);
            sc[nl] = 1.f / (1.f + __expf(-v));
        }
    }
    __syncthreads();
    // B: rank-based top-k
    if (tid < nper) {
        float mine = sc[tid];
        int rank = 0;
        for (int j = 0; j < nper; j++) {
            float sj = sc[j];
            rank += (sj > mine) || (sj == mine && j < tid);
        }
        int node = gi * nper + tid;
        if (stage == 0) g_newidx[node] = (rank < k) ? gi * k + rank : -1;
        if (rank < k) {
            if (stage == 0) g_perm1[gi * k + rank] = node;
            pm[rank] = node;
            ss[rank] = mine;
        }
    }
    __syncthreads();
    // C: build stage-2 CSR for this graph (stage 0 only)
    if (stage == 0) {
        for (int i = tid; i < k; i += 512) cnt[i] = 0;
        __syncthreads();
        int e0 = gi * EPG_, e1 = e0 + EPG_;
        for (int e = e0 + tid; e < e1; e += 512) {
            int ns = g_newidx[src[e]], nd = g_newidx[dst[e]];
            if (ns >= 0 && nd >= 0) atomicAdd(&cnt[nd - gi * k], 1);
        }
        __syncthreads();
        s[tid] = (tid < k) ? cnt[tid] : 0;
        __syncthreads();
        for (int d = 1; d < 256; d <<= 1) {
            int u = (tid >= d) ? s[tid - d] : 0;
            __syncthreads();
            s[tid] += u;
            __syncthreads();
        }
        if (tid < k) offs[tid + 1] = s[tid];
        if (tid == 0) offs[0] = 0;
        __syncthreads();
        for (int i = tid; i < k; i += 512) {
            g_off2[gi * k + i] = gi * EPG_ + offs[i];
            g_deg2[gi * k + i] = cnt[i];
            cnt[i] = 0;
        }
        __syncthreads();
        for (int e = e0 + tid; e < e1; e += 512) {
            int ns = g_newidx[src[e]], nd = g_newidx[dst[e]];
            if (ns >= 0 && nd >= 0) {
                int l = nd - gi * k;
                int p = atomicAdd(&cnt[l], 1);
                g_el2[gi * EPG_ + offs[l] + p] = e;
            }
        }
    }
    // D: gather(*score) + readout (max || mean)
    if (tid < D_) {
        float mx = -3.4e38f, sm = 0.f;
        for (int j = 0; j < k; j++) {
            float v = g_conv[(size_t)pm[j] * D_ + tid] * ss[j];
            if (stage == 0) g_hp[(size_t)(gi * k + j) * D_ + tid] = v;
            mx = fmaxf(mx, v);
            sm += v;
        }
        g_z[gi * 1328 + zoff + tid] = mx;
        g_z[gi * 1328 + zoff + D_ + tid] = sm * inv;
    }
}

// ---------------- MLP head ----------------
__global__ void k_head(const float* __restrict__ fc1W, const float* __restrict__ fc1b,
                       const float* __restrict__ bn1g, const float* __restrict__ bn1b,
                       const float* __restrict__ fc2W, const float* __restrict__ fc2b,
                       const float* __restrict__ bn2g, const float* __restrict__ bn2b,
                       const float* __restrict__ fc3W, const float* __restrict__ fc3b,
                       float* __restrict__ out) {
    __shared__ float zs[2][1328];
    __shared__ float p1[2][2][D_];     // [half][row][o]
    __shared__ float a1[2][D_];
    __shared__ float a2[2][D3_];
    int t = threadIdx.x;               // 704
    for (int i = t; i < 2 * 1328; i += 704) zs[i / 1328][i % 1328] = g_z[i];
    __syncthreads();
    if (t < 2 * D_) {
        int half = t / D_, o = t - half * D_;
        int i0 = half * 664, i1 = i0 + 664;
        float a0 = 0.f, a1v = 0.f;
        for (int i = i0; i < i1; i++) {
            float wv = fc1W[i * D_ + o];
            a0 += zs[0][i] * wv;
            a1v += zs[1][i] * wv;
        }
        p1[half][0][o] = a0;
        p1[half][1][o] = a1v;
    }
    __syncthreads();
    if (t < D_) {
        float v0 = fc1b[t] + p1[0][0][t] + p1[1][0][t];
        float v1 = fc1b[t] + p1[0][1][t] + p1[1][1][t];
        float m = (v0 + v1) * 0.5f;
        float d0 = v0 - m, d1 = v1 - m;
        float var = (d0 * d0 + d1 * d1) * 0.5f;
        float is = rsqrtf(var + 1e-5f);
        a1[0][t] = fmaxf(d0 * is * bn1g[t] + bn1b[t], 0.f);
        a1[1][t] = fmaxf(d1 * is * bn1g[t] + bn1b[t], 0.f);
    }
    __syncthreads();
    if (t < 2 * D3_) {
        int r = t / D3_, o = t - r * D3_;
        float acc = fc2b[o];
        for (int i = 0; i < D_; i++) acc += a1[r][i] * fc2W[i * D3_ + o];
        a2[r][o] = acc;
    }
    __syncthreads();
    if (t < D3_) {
        float m = (a2[0][t] + a2[1][t]) * 0.5f;
        float d0 = a2[0][t] - m, d1 = a2[1][t] - m;
        float var = (d0 * d0 + d1 * d1) * 0.5f;
        float is = rsqrtf(var + 1e-5f);
        a2[0][t] = fmaxf(d0 * is * bn2g[t] + bn2b[t], 0.f);
        a2[1][t] = fmaxf(d1 * is * bn2g[t] + bn2b[t], 0.f);
    }
    __syncthreads();
    if (t < 4) {
        int r = t >> 1, o = t & 1;
        float acc = fc3b[o];
        for (int i = 0; i < D3_; i++) acc += a2[r][i] * fc3W[i * 2 + o];
        out[r * 2 + o] = acc;
    }
}

extern "C" void kernel_launch(void* const* d_in, const int* in_sizes, int n_in,
                              void* d_out, int out_size) {
    const float* x    = (const float*)d_in[0];
    const int*   ei   = (const int*)d_in[1];
    const float* eat  = (const float*)d_in[3];
    const float* pos  = (const float*)d_in[4];
    const float* c1W1 = (const float*)d_in[6];
    const float* c1W2 = (const float*)d_in[7];
    const float* c1nb = (const float*)d_in[8];
    const float* c1b  = (const float*)d_in[9];
    const float* p1w  = (const float*)d_in[10];
    const float* c2W1 = (const float*)d_in[11];
    const float* c2W2 = (const float*)d_in[12];
    const float* c2nb = (const float*)d_in[13];
    const float* c2b  = (const float*)d_in[14];
    const float* p2w  = (const float*)d_in[15];
    const float* fc1W = (const float*)d_in[16];
    const float* fc1b = (const float*)d_in[17];
    const float* bn1g = (const float*)d_in[18];
    const float* bn1b = (const float*)d_in[19];
    const float* fc2W = (const float*)d_in[20];
    const float* fc2b = (const float*)d_in[21];
    const float* bn2g = (const float*)d_in[22];
    const float* bn2b = (const float*)d_in[23];
    const float* fc3W = (const float*)d_in[24];
    const float* fc3b = (const float*)d_in[25];
    const int* src = ei;
    const int* dst = ei + NE_;
    float* out = (float*)d_out;

    // stage 1: conv1
    k_csr<<<1, 1024>>>(dst);
    k_gates_expand<<<NN_, 256>>>(pos, c1W1, x, 0);
    k_gemm<<<dim3((D_ + 63) / 64, (NN_ + 63) / 64, SK), 128>>>(c1W2, c1nb, NN_);
    k_reduce<<<(NN_ * (D_ / 4) + 255) / 256, 256>>>(NN_);
    k_agg<<<NN_, 256>>>(eat, src, c1b, NN_, 0);

    // pool1: score + select + CSR2 + gather + readout
    k_pool<<<G_, 512>>>(p1w, src, dst, NP_, K1_, 0, 0, 1.f / (float)K1_);

    // stage 2: conv2
    k_gates_expand<<<NP_, 256>>>(pos, c2W1, nullptr, 1);
    k_gemm<<<dim3((D_ + 63) / 64, (NP_ + 63) / 64, SK), 128>>>(c2W2, c2nb, NP_);
    k_reduce<<<(NP_ * (D_ / 4) + 255) / 256, 256>>>(NP_);
    k_agg<<<NP_, 256>>>(eat, src, c2b, NP_, 1);

    // pool2: score + select + gather + readout
    k_pool<<<G_, 512>>>(p2w, src, dst, K1_, K2_, 1, 2 * D_, 1.f / (float)K2_);

    // MLP head
    k_head<<<1, 704>>>(fc1W, fc1b, bn1g, bn1b, fc2W, fc2b, bn2g, bn2b, fc3W, fc3b, out);
}